// round 5
// baseline (speedup 1.0000x reference)
#include <cuda_runtime.h>
#include <math.h>

// ---------------- static scratch (no allocations allowed) ----------------
#define MAXN 100000
#define MAXE 1600000

__device__ float g_h [(size_t)MAXN * 128];   // current layer features (<=128 wide)
__device__ float g_hp[(size_t)MAXN * 64];    // activated layer output (64 wide)
__device__ float g_asrc[MAXN * 8];
__device__ float g_adst[MAXN * 8];
__device__ int   g_deg[MAXN];
__device__ int   g_off[MAXN + 1];
__device__ int   g_cur[MAXN];
__device__ int   g_csr[MAXE];

__device__ __forceinline__ float lrelu(float x) { return x > 0.f ? x : 0.2f * x; }

__device__ __forceinline__ unsigned f2tf32(float x) {
    unsigned r;
    asm("cvt.rna.tf32.f32 %0, %1;" : "=r"(r) : "f"(x));
    return r;
}

#define MMA_TF32(c, a, b)                                                  \
    asm volatile(                                                          \
        "mma.sync.aligned.m16n8k8.row.col.f32.tf32.tf32.f32 "              \
        "{%0,%1,%2,%3}, {%4,%5,%6,%7}, {%8,%9}, {%0,%1,%2,%3};"            \
        : "+f"(c[0]), "+f"(c[1]), "+f"(c[2]), "+f"(c[3])                   \
        : "r"(a[0]), "r"(a[1]), "r"(a[2]), "r"(a[3]), "r"(b[0]), "r"(b[1]))

// ---------------- CSR build ----------------
__global__ void k_zero_deg(int N) {
    int i = blockIdx.x * blockDim.x + threadIdx.x;
    if (i < N) g_deg[i] = 0;
}

__global__ void k_count(const int* __restrict__ ei, int E) {
    int e = blockIdx.x * blockDim.x + threadIdx.x;
    if (e < E) atomicAdd(&g_deg[ei[E + e]], 1);
}

// one block, 1024 threads: exclusive scan of degrees -> g_off, copy -> g_cur
__global__ void k_scan(int N, int E) {
    __shared__ int ssum[1024];
    int t = threadIdx.x;
    int chunk = (N + 1023) / 1024;
    int lo = t * chunk;
    int hi = min(lo + chunk, N);
    int s = 0;
    for (int i = lo; i < hi; i++) s += g_deg[i];
    ssum[t] = s;
    __syncthreads();
    for (int d = 1; d < 1024; d <<= 1) {
        int v = (t >= d) ? ssum[t - d] : 0;
        __syncthreads();
        ssum[t] += v;
        __syncthreads();
    }
    int run = ssum[t] - s;  // exclusive prefix
    for (int i = lo; i < hi; i++) {
        g_off[i] = run;
        g_cur[i] = run;
        run += g_deg[i];
    }
    if (t == 0) g_off[N] = E;
}

__global__ void k_scatter(const int* __restrict__ ei, int E) {
    int e = blockIdx.x * blockDim.x + threadIdx.x;
    if (e < E) {
        int src = ei[e];
        int dst = ei[E + e];
        int pos = atomicAdd(&g_cur[dst], 1);
        g_csr[pos] = src;
    }
}

// ---------------- TF32 tensor-core GEMM with 3xTF32 compensation ----------------
// C[M,N] = [A1|A2] @ W.  K1,K2 multiples of 32.  Tile 128x64, 256 thr, 8 warps (4x2).
// smem holds pre-swizzled mma fragments so frag loads are conflict-free LDS.128/64.
__global__ void k_mma(const float* __restrict__ A1, int K1,
                      const float* __restrict__ A2, int K2,
                      const float* __restrict__ W, int Ncols,
                      float* __restrict__ Cmat, int M) {
    // [hi/lo][k8-block 0..3][m16 tile 0..7][lane][reg]
    __shared__ unsigned sA[2][4][8][32][4];   // 32 KB
    __shared__ unsigned sB[2][4][8][32][2];   // 16 KB

    const int tid  = threadIdx.x;
    const int lane = tid & 31;
    const int wid  = tid >> 5;
    const int wm   = wid >> 1;   // 0..3  (32-row strip)
    const int wn   = wid & 1;    // 0..1  (32-col strip)
    const int row0 = blockIdx.x * 128;
    const int col0 = blockIdx.y * 64;
    const int K    = K1 + K2;

    float acc[2][4][4];
#pragma unroll
    for (int i = 0; i < 2; i++)
#pragma unroll
        for (int j = 0; j < 4; j++)
#pragma unroll
            for (int r = 0; r < 4; r++) acc[i][j][r] = 0.f;

    const int fa_row = tid >> 1;           // 0..127
    const int fa_cg  = (tid & 1) * 16;     // 0 or 16
    const int fb_k   = tid >> 3;           // 0..31
    const int fb_n0  = (tid & 7) * 8;      // 0..56

    for (int k0 = 0; k0 < K; k0 += 32) {
        // ---- fill A tile (128 x 32), hi/lo tf32, swizzled to frag layout ----
        {
            int grow = row0 + fa_row;
            int t  = fa_row >> 4;
            int rr = fa_row & 15;
#pragma unroll
            for (int q = 0; q < 4; q++) {
                int kk = fa_cg + q * 4;
                int kg = k0 + kk;
                float4 v = make_float4(0.f, 0.f, 0.f, 0.f);
                if (grow < M) {
                    const float* p = (kg < K1) ? (A1 + (size_t)grow * K1 + kg)
                                               : (A2 + (size_t)grow * K2 + (kg - K1));
                    v = *(const float4*)p;
                }
                float vv[4] = {v.x, v.y, v.z, v.w};
#pragma unroll
                for (int u = 0; u < 4; u++) {
                    int kc  = kk + u;
                    int kb  = kc >> 3, kin = kc & 7;
                    int ln  = ((rr & 7) << 2) | (kin & 3);
                    int rg  = (rr >> 3) | ((kin >> 2) << 1);
                    unsigned hi = f2tf32(vv[u]);
                    float lo = vv[u] - __uint_as_float(hi);
                    sA[0][kb][t][ln][rg] = hi;
                    sA[1][kb][t][ln][rg] = f2tf32(lo);
                }
            }
        }
        // ---- fill B tile (32 x 64) ----
        {
            int kb = fb_k >> 3, kin = fb_k & 7;
#pragma unroll
            for (int q = 0; q < 2; q++) {
                int n0 = fb_n0 + q * 4;
                float4 v = *(const float4*)(W + (size_t)(k0 + fb_k) * Ncols + col0 + n0);
                float vv[4] = {v.x, v.y, v.z, v.w};
#pragma unroll
                for (int u = 0; u < 4; u++) {
                    int n  = n0 + u;
                    int nt = n >> 3, nn = n & 7;
                    int ln = (nn << 2) | (kin & 3);
                    int rg = kin >> 2;
                    unsigned hi = f2tf32(vv[u]);
                    float lo = vv[u] - __uint_as_float(hi);
                    sB[0][kb][nt][ln][rg] = hi;
                    sB[1][kb][nt][ln][rg] = f2tf32(lo);
                }
            }
        }
        __syncthreads();

#pragma unroll
        for (int kb = 0; kb < 4; kb++) {
            unsigned ah[2][4], al[2][4], bh[4][2], bl[4][2];
#pragma unroll
            for (int i = 0; i < 2; i++) {
                uint4 x = *(const uint4*)&sA[0][kb][wm * 2 + i][lane][0];
                ah[i][0] = x.x; ah[i][1] = x.y; ah[i][2] = x.z; ah[i][3] = x.w;
                uint4 y = *(const uint4*)&sA[1][kb][wm * 2 + i][lane][0];
                al[i][0] = y.x; al[i][1] = y.y; al[i][2] = y.z; al[i][3] = y.w;
            }
#pragma unroll
            for (int j = 0; j < 4; j++) {
                uint2 x = *(const uint2*)&sB[0][kb][wn * 4 + j][lane][0];
                bh[j][0] = x.x; bh[j][1] = x.y;
                uint2 y = *(const uint2*)&sB[1][kb][wn * 4 + j][lane][0];
                bl[j][0] = y.x; bl[j][1] = y.y;
            }
#pragma unroll
            for (int i = 0; i < 2; i++)
#pragma unroll
                for (int j = 0; j < 4; j++) {
                    MMA_TF32(acc[i][j], ah[i], bh[j]);
                    MMA_TF32(acc[i][j], ah[i], bl[j]);
                    MMA_TF32(acc[i][j], al[i], bh[j]);
                }
        }
        __syncthreads();
    }

    // ---- epilogue ----
#pragma unroll
    for (int i = 0; i < 2; i++) {
        int r = row0 + wm * 32 + i * 16 + (lane >> 2);
#pragma unroll
        for (int j = 0; j < 4; j++) {
            int c = col0 + wn * 32 + j * 8 + (lane & 3) * 2;
            if (r < M)
                *(float2*)(Cmat + (size_t)r * Ncols + c) = make_float2(acc[i][j][0], acc[i][j][1]);
            if (r + 8 < M)
                *(float2*)(Cmat + (size_t)(r + 8) * Ncols + c) = make_float2(acc[i][j][2], acc[i][j][3]);
        }
    }
}

// ---------------- attention scores: a_src/a_dst [N,8] ----------------
template <int C>
__global__ void k_att(const float* __restrict__ hf, const float* __restrict__ att_s,
                      const float* __restrict__ att_d, int N) {
    int idx = blockIdx.x * blockDim.x + threadIdx.x;
    if (idx >= N * 8) return;
    int hh = idx & 7;
    const float* hp = hf + (size_t)(idx >> 3) * 8 * C + hh * C;
    float s = 0.f, d = 0.f;
#pragma unroll
    for (int c = 0; c < C; c++) {
        float v = hp[c];
        s += v * att_s[hh * C + c];
        d += v * att_d[hh * C + c];
    }
    g_asrc[idx] = s;
    g_adst[idx] = d;
}

// ---------------- aggregation: warp per node, two-pass softmax ----------------
// MODE 0: concat(8*C) + bias + PReLU -> out[N, 8*C]
// MODE 1: mean over heads + bias + log_softmax -> out[N, C]   (C=16)
template <int C, int MODE>
__global__ void k_agg(const float* __restrict__ hf, const float* __restrict__ bias,
                      const float* __restrict__ prelu_p, float* __restrict__ out, int N) {
    constexpr int F = 8 * C;
    constexpr int FPL = F / 32;
    int wib = threadIdx.x >> 5;
    int lane = threadIdx.x & 31;
    int n = blockIdx.x * (blockDim.x >> 5) + wib;
    if (n >= N) return;

    int start = g_off[n];
    int deg = g_off[n + 1] - start;

    int hh = lane & 7;
    float adst_h = g_adst[n * 8 + hh];

    // ---- pass 1: per-head max (self-loop included); lanes = (edge%4, head) ----
    float m = lrelu(g_asrc[n * 8 + hh] + adst_h);
    {
        int j = lane >> 3;  // 0..3
        for (; j + 8 <= deg; j += 8) {
            int sa = g_csr[start + j];
            int sb = g_csr[start + j + 4];
            float ea = lrelu(g_asrc[sa * 8 + hh] + adst_h);
            float eb = lrelu(g_asrc[sb * 8 + hh] + adst_h);
            m = fmaxf(m, fmaxf(ea, eb));
        }
        for (; j < deg; j += 4) {
            int s = g_csr[start + j];
            m = fmaxf(m, lrelu(g_asrc[s * 8 + hh] + adst_h));
        }
    }
    m = fmaxf(m, __shfl_xor_sync(0xffffffffu, m, 8));
    m = fmaxf(m, __shfl_xor_sync(0xffffffffu, m, 16));

    // ---- pass 2: accumulate exp weights and weighted features (unroll x4) ----
    float acc[FPL];
#pragma unroll
    for (int i = 0; i < FPL; i++) acc[i] = 0.f;
    float sreg = 0.f;

    // self-loop
    {
        float w = __expf(lrelu(g_asrc[n * 8 + hh] + adst_h) - m);
        sreg += w;
#pragma unroll
        for (int i = 0; i < FPL; i++) {
            int f = lane + 32 * i;
            float wi = __shfl_sync(0xffffffffu, w, f / C);
            acc[i] += wi * hf[(size_t)n * F + f];
        }
    }
    int j = 0;
    for (; j + 4 <= deg; j += 4) {
        int s0 = g_csr[start + j + 0];
        int s1 = g_csr[start + j + 1];
        int s2 = g_csr[start + j + 2];
        int s3 = g_csr[start + j + 3];
        float f0[FPL], f1[FPL], f2[FPL], f3[FPL];
#pragma unroll
        for (int i = 0; i < FPL; i++) {
            int f = lane + 32 * i;
            f0[i] = hf[(size_t)s0 * F + f];
            f1[i] = hf[(size_t)s1 * F + f];
            f2[i] = hf[(size_t)s2 * F + f];
            f3[i] = hf[(size_t)s3 * F + f];
        }
        float w0 = __expf(lrelu(g_asrc[s0 * 8 + hh] + adst_h) - m);
        float w1 = __expf(lrelu(g_asrc[s1 * 8 + hh] + adst_h) - m);
        float w2 = __expf(lrelu(g_asrc[s2 * 8 + hh] + adst_h) - m);
        float w3 = __expf(lrelu(g_asrc[s3 * 8 + hh] + adst_h) - m);
        sreg += (w0 + w1) + (w2 + w3);
#pragma unroll
        for (int i = 0; i < FPL; i++) {
            int hsel = (lane + 32 * i) / C;
            acc[i] += __shfl_sync(0xffffffffu, w0, hsel) * f0[i];
            acc[i] += __shfl_sync(0xffffffffu, w1, hsel) * f1[i];
            acc[i] += __shfl_sync(0xffffffffu, w2, hsel) * f2[i];
            acc[i] += __shfl_sync(0xffffffffu, w3, hsel) * f3[i];
        }
    }
    for (; j < deg; j++) {
        int s = g_csr[start + j];
        float w = __expf(lrelu(g_asrc[s * 8 + hh] + adst_h) - m);
        sreg += w;
#pragma unroll
        for (int i = 0; i < FPL; i++) {
            int f = lane + 32 * i;
            float wi = __shfl_sync(0xffffffffu, w, f / C);
            acc[i] += wi * hf[(size_t)s * F + f];
        }
    }

    if (MODE == 0) {
        float pa = prelu_p[0];
#pragma unroll
        for (int i = 0; i < FPL; i++) {
            int f = lane + 32 * i;
            float sden = __shfl_sync(0xffffffffu, sreg, f / C) + 1e-16f;
            float v = acc[i] / sden + bias[f];
            out[(size_t)n * F + f] = (v >= 0.f) ? v : pa * v;
        }
    } else {
        // mean over 8 heads, +bias, log_softmax over C=16 columns
        float vsum = 0.f;
#pragma unroll
        for (int i = 0; i < FPL; i++) {
            int f = lane + 32 * i;
            float sden = __shfl_sync(0xffffffffu, sreg, f / C) + 1e-16f;
            vsum += acc[i] / sden;
        }
        vsum += __shfl_xor_sync(0xffffffffu, vsum, 16);
        int c = lane & 15;
        float val = vsum * 0.125f + bias[c];
        float mx = val;
#pragma unroll
        for (int o = 8; o >= 1; o >>= 1) mx = fmaxf(mx, __shfl_xor_sync(0xffffffffu, mx, o));
        float se = expf(val - mx);
#pragma unroll
        for (int o = 8; o >= 1; o >>= 1) se += __shfl_xor_sync(0xffffffffu, se, o);
        float res = val - mx - logf(se);
        if (lane < 16) out[(size_t)n * C + c] = res;
    }
}

// ---------------- launch ----------------
extern "C" void kernel_launch(void* const* d_in, const int* in_sizes, int n_in,
                              void* d_out, int out_size) {
    const float* x   = (const float*)d_in[0];
    const int*   ei  = (const int*)d_in[1];
    const float* W1  = (const float*)d_in[2];
    const float* as1 = (const float*)d_in[3];
    const float* ad1 = (const float*)d_in[4];
    const float* b1  = (const float*)d_in[5];
    const float* W2  = (const float*)d_in[6];
    const float* as2 = (const float*)d_in[7];
    const float* ad2 = (const float*)d_in[8];
    const float* b2  = (const float*)d_in[9];
    const float* W3  = (const float*)d_in[10];
    const float* as3 = (const float*)d_in[11];
    const float* ad3 = (const float*)d_in[12];
    const float* b3  = (const float*)d_in[13];
    const float* p1  = (const float*)d_in[14];
    const float* p2  = (const float*)d_in[15];
    float* out = (float*)d_out;

    int N = in_sizes[0] / 256;
    int E = in_sizes[1] / 2;

    float *hbuf, *hpbuf;
    cudaGetSymbolAddress((void**)&hbuf, g_h);
    cudaGetSymbolAddress((void**)&hpbuf, g_hp);

    int gb256N = (N + 255) / 256;
    int gb256E = (E + 255) / 256;
    int gbAtt = (N * 8 + 255) / 256;
    int gbAgg = (N + 7) / 8;           // 8 warps/block
    int gbM = (N + 127) / 128;

    // CSR by destination (shared by all 3 layers)
    k_zero_deg<<<gb256N, 256>>>(N);
    k_count<<<gb256E, 256>>>(ei, E);
    k_scan<<<1, 1024>>>(N, E);
    k_scatter<<<gb256E, 256>>>(ei, E);

    // Layer 1: h1 = x@W1 -> agg -> PReLU -> hp
    k_mma<<<dim3(gbM, 1), 256>>>(x, 256, nullptr, 0, W1, 64, hbuf, N);
    k_att<8><<<gbAtt, 256>>>(hbuf, as1, ad1, N);
    k_agg<8, 0><<<gbAgg, 256>>>(hbuf, b1, p1, hpbuf, N);

    // Layer 2: h2 = [x|hp]@W2 -> agg -> PReLU -> hp
    k_mma<<<dim3(gbM, 1), 256>>>(x, 256, hpbuf, 64, W2, 64, hbuf, N);
    k_att<8><<<gbAtt, 256>>>(hbuf, as2, ad2, N);
    k_agg<8, 0><<<gbAgg, 256>>>(hbuf, b2, p2, hpbuf, N);

    // Layer 3: h3 = hp@W3 -> agg(mean) -> log_softmax -> out
    k_mma<<<dim3(gbM, 2), 256>>>(hpbuf, 64, nullptr, 0, W3, 128, hbuf, N);
    k_att<16><<<gbAtt, 256>>>(hbuf, as3, ad3, N);
    k_agg<16, 1><<<gbAgg, 256>>>(hbuf, b3, nullptr, out, N);
}

// round 7
// speedup vs baseline: 1.7410x; 1.7410x over previous
#include <cuda_runtime.h>
#include <math.h>

// ---------------- static scratch (no allocations allowed) ----------------
#define MAXN 100000
#define MAXE 1600000

__device__ float g_h [(size_t)MAXN * 128];   // current layer features (<=128 wide)
__device__ float g_hp[(size_t)MAXN * 64];    // activated layer output (64 wide)
__device__ float g_asrc[MAXN * 8];
__device__ float g_adst[MAXN * 8];
__device__ int   g_deg[MAXN];
__device__ int   g_off[MAXN + 1];
__device__ int   g_cur[MAXN];
__device__ int   g_csr[MAXE];

__device__ __forceinline__ float lrelu(float x) { return x > 0.f ? x : 0.2f * x; }

// ---------------- CSR build ----------------
__global__ void k_count(const int* __restrict__ ei, int E) {
    int e = blockIdx.x * blockDim.x + threadIdx.x;
    if (e < E) atomicAdd(&g_deg[ei[E + e]], 1);
}

// one block, 1024 threads: exclusive scan of degrees -> g_off, copy -> g_cur
__global__ void k_scan(int N, int E) {
    __shared__ int ssum[1024];
    int t = threadIdx.x;
    int chunk = (N + 1023) / 1024;
    int lo = t * chunk;
    int hi = min(lo + chunk, N);
    int s = 0;
    for (int i = lo; i < hi; i++) s += g_deg[i];
    ssum[t] = s;
    __syncthreads();
    for (int d = 1; d < 1024; d <<= 1) {
        int v = (t >= d) ? ssum[t - d] : 0;
        __syncthreads();
        ssum[t] += v;
        __syncthreads();
    }
    int run = ssum[t] - s;  // exclusive prefix
    for (int i = lo; i < hi; i++) {
        g_off[i] = run;
        g_cur[i] = run;
        run += g_deg[i];
    }
    if (t == 0) g_off[N] = E;
}

__global__ void k_scatter(const int* __restrict__ ei, int E) {
    int e = blockIdx.x * blockDim.x + threadIdx.x;
    if (e < E) {
        int src = ei[e];
        int dst = ei[E + e];
        int pos = atomicAdd(&g_cur[dst], 1);
        g_csr[pos] = src;
    }
}

// ---------------- FFMA SGEMM v2: C[M,N] = [A1|A2] @ W ----------------
// Tile 128x64, 128 threads, 8x8 microtile, double-buffered smem,
// register-staged global prefetch, one __syncthreads per K-tile.
__global__ __launch_bounds__(128) void k_sgemm(const float* __restrict__ A1, int K1,
                                               const float* __restrict__ A2, int K2,
                                               const float* __restrict__ W, int Ncols,
                                               float* __restrict__ Cmat, int M) {
    __shared__ float As[2][16][128];  // [buf][k][row]
    __shared__ float Ws[2][16][64];   // [buf][k][col]

    const int tid  = threadIdx.x;
    const int tx   = tid & 7;    // 8 cols
    const int ty   = tid >> 3;   // 8 rows
    const int row0 = blockIdx.x * 128;
    const int col0 = blockIdx.y * 64;
    const int K    = K1 + K2;
    const int T    = K >> 4;

    float acc[8][8];
#pragma unroll
    for (int i = 0; i < 8; i++)
#pragma unroll
        for (int j = 0; j < 8; j++) acc[i][j] = 0.f;

    float4 ra[4];
    float4 rb[2];

    auto ldTile = [&](int t) {
        int k0 = t << 4;
#pragma unroll
        for (int p = 0; p < 4; p++) {
            int idx = tid + 128 * p;         // 0..511
            int r   = idx >> 2;              // 0..127
            int kk  = (idx & 3) * 4;
            int kg  = k0 + kk;
            int grow = row0 + r;
            float4 v = make_float4(0.f, 0.f, 0.f, 0.f);
            if (grow < M) {
                const float* s = (kg < K1) ? (A1 + (size_t)grow * K1 + kg)
                                           : (A2 + (size_t)grow * K2 + (kg - K1));
                v = *(const float4*)s;
            }
            ra[p] = v;
        }
#pragma unroll
        for (int q = 0; q < 2; q++) {
            int idx = tid + 128 * q;         // 0..255
            int kk  = idx >> 4;              // 0..15
            int c4  = (idx & 15) * 4;
            rb[q] = *(const float4*)(W + (size_t)(k0 + kk) * Ncols + col0 + c4);
        }
    };
    auto stTile = [&](int b) {
#pragma unroll
        for (int p = 0; p < 4; p++) {
            int idx = tid + 128 * p;
            int r   = idx >> 2;
            int kk  = (idx & 3) * 4;
            As[b][kk + 0][r] = ra[p].x;
            As[b][kk + 1][r] = ra[p].y;
            As[b][kk + 2][r] = ra[p].z;
            As[b][kk + 3][r] = ra[p].w;
        }
#pragma unroll
        for (int q = 0; q < 2; q++) {
            int idx = tid + 128 * q;
            int kk  = idx >> 4;
            int c4  = (idx & 15) * 4;
            *(float4*)&Ws[b][kk][c4] = rb[q];
        }
    };

    ldTile(0);
    stTile(0);
    __syncthreads();

    int buf = 0;
    for (int t = 0; t < T; t++) {
        if (t + 1 < T) ldTile(t + 1);  // LDG into regs, hidden under compute
#pragma unroll
        for (int k = 0; k < 16; k++) {
            float a[8], b[8];
            *(float4*)&a[0] = *(const float4*)&As[buf][k][ty * 8];
            *(float4*)&a[4] = *(const float4*)&As[buf][k][ty * 8 + 4];
            *(float4*)&b[0] = *(const float4*)&Ws[buf][k][tx * 8];
            *(float4*)&b[4] = *(const float4*)&Ws[buf][k][tx * 8 + 4];
#pragma unroll
            for (int i = 0; i < 8; i++)
#pragma unroll
                for (int j = 0; j < 8; j++) acc[i][j] += a[i] * b[j];
        }
        if (t + 1 < T) stTile(buf ^ 1);
        __syncthreads();
        buf ^= 1;
    }

    // epilogue: 8 rows x 8 cols per thread, two float4 per row
#pragma unroll
    for (int i = 0; i < 8; i++) {
        int grow = row0 + ty * 8 + i;
        if (grow < M) {
            float* p = Cmat + (size_t)grow * Ncols + col0 + tx * 8;
            *(float4*)p       = make_float4(acc[i][0], acc[i][1], acc[i][2], acc[i][3]);
            *(float4*)(p + 4) = make_float4(acc[i][4], acc[i][5], acc[i][6], acc[i][7]);
        }
    }
}

// ---------------- attention scores: a_src/a_dst [N,8] ----------------
template <int C>
__global__ void k_att(const float* __restrict__ hf, const float* __restrict__ att_s,
                      const float* __restrict__ att_d, int N) {
    int idx = blockIdx.x * blockDim.x + threadIdx.x;
    if (idx >= N * 8) return;
    int hh = idx & 7;
    const float* hp = hf + (size_t)(idx >> 3) * 8 * C + hh * C;
    float s = 0.f, d = 0.f;
#pragma unroll
    for (int c = 0; c < C; c++) {
        float v = hp[c];
        s += v * att_s[hh * C + c];
        d += v * att_d[hh * C + c];
    }
    g_asrc[idx] = s;
    g_adst[idx] = d;
}

// ---------------- aggregation: warp per node, two-pass softmax ----------------
// MODE 0: concat(8*C) + bias + PReLU -> out[N, 8*C]
// MODE 1: mean over heads + bias + log_softmax -> out[N, C]   (C=16)
template <int C, int MODE>
__global__ void k_agg(const float* __restrict__ hf, const float* __restrict__ bias,
                      const float* __restrict__ prelu_p, float* __restrict__ out, int N) {
    constexpr int F = 8 * C;
    constexpr int FPL = F / 32;
    int wib = threadIdx.x >> 5;
    int lane = threadIdx.x & 31;
    int n = blockIdx.x * (blockDim.x >> 5) + wib;
    if (n >= N) return;

    int start = g_off[n];
    int deg = g_off[n + 1] - start;

    int hh = lane & 7;
    float adst_h = g_adst[n * 8 + hh];

    // ---- pass 1: per-head max (self-loop included); lanes = (edge%4, head) ----
    float m = lrelu(g_asrc[n * 8 + hh] + adst_h);
    {
        int j = lane >> 3;  // 0..3
        for (; j + 8 <= deg; j += 8) {
            int sa = g_csr[start + j];
            int sb = g_csr[start + j + 4];
            float ea = lrelu(g_asrc[sa * 8 + hh] + adst_h);
            float eb = lrelu(g_asrc[sb * 8 + hh] + adst_h);
            m = fmaxf(m, fmaxf(ea, eb));
        }
        for (; j < deg; j += 4) {
            int s = g_csr[start + j];
            m = fmaxf(m, lrelu(g_asrc[s * 8 + hh] + adst_h));
        }
    }
    m = fmaxf(m, __shfl_xor_sync(0xffffffffu, m, 8));
    m = fmaxf(m, __shfl_xor_sync(0xffffffffu, m, 16));

    // ---- pass 2: accumulate exp weights and weighted features (unroll x4) ----
    float acc[FPL];
#pragma unroll
    for (int i = 0; i < FPL; i++) acc[i] = 0.f;
    float sreg = 0.f;

    // self-loop
    {
        float w = __expf(lrelu(g_asrc[n * 8 + hh] + adst_h) - m);
        sreg += w;
#pragma unroll
        for (int i = 0; i < FPL; i++) {
            int f = lane + 32 * i;
            float wi = __shfl_sync(0xffffffffu, w, f / C);
            acc[i] += wi * hf[(size_t)n * F + f];
        }
    }
    int j = 0;
    for (; j + 4 <= deg; j += 4) {
        int s0 = g_csr[start + j + 0];
        int s1 = g_csr[start + j + 1];
        int s2 = g_csr[start + j + 2];
        int s3 = g_csr[start + j + 3];
        float f0[FPL], f1[FPL], f2[FPL], f3[FPL];
#pragma unroll
        for (int i = 0; i < FPL; i++) {
            int f = lane + 32 * i;
            f0[i] = hf[(size_t)s0 * F + f];
            f1[i] = hf[(size_t)s1 * F + f];
            f2[i] = hf[(size_t)s2 * F + f];
            f3[i] = hf[(size_t)s3 * F + f];
        }
        float w0 = __expf(lrelu(g_asrc[s0 * 8 + hh] + adst_h) - m);
        float w1 = __expf(lrelu(g_asrc[s1 * 8 + hh] + adst_h) - m);
        float w2 = __expf(lrelu(g_asrc[s2 * 8 + hh] + adst_h) - m);
        float w3 = __expf(lrelu(g_asrc[s3 * 8 + hh] + adst_h) - m);
        sreg += (w0 + w1) + (w2 + w3);
#pragma unroll
        for (int i = 0; i < FPL; i++) {
            int hsel = (lane + 32 * i) / C;
            acc[i] += __shfl_sync(0xffffffffu, w0, hsel) * f0[i];
            acc[i] += __shfl_sync(0xffffffffu, w1, hsel) * f1[i];
            acc[i] += __shfl_sync(0xffffffffu, w2, hsel) * f2[i];
            acc[i] += __shfl_sync(0xffffffffu, w3, hsel) * f3[i];
        }
    }
    for (; j < deg; j++) {
        int s = g_csr[start + j];
        float w = __expf(lrelu(g_asrc[s * 8 + hh] + adst_h) - m);
        sreg += w;
#pragma unroll
        for (int i = 0; i < FPL; i++) {
            int f = lane + 32 * i;
            float wi = __shfl_sync(0xffffffffu, w, f / C);
            acc[i] += wi * hf[(size_t)s * F + f];
        }
    }

    if (MODE == 0) {
        float pa = prelu_p[0];
#pragma unroll
        for (int i = 0; i < FPL; i++) {
            int f = lane + 32 * i;
            float sden = __shfl_sync(0xffffffffu, sreg, f / C) + 1e-16f;
            float v = acc[i] / sden + bias[f];
            out[(size_t)n * F + f] = (v >= 0.f) ? v : pa * v;
        }
    } else {
        // mean over 8 heads, +bias, log_softmax over C=16 columns
        float vsum = 0.f;
#pragma unroll
        for (int i = 0; i < FPL; i++) {
            int f = lane + 32 * i;
            float sden = __shfl_sync(0xffffffffu, sreg, f / C) + 1e-16f;
            vsum += acc[i] / sden;
        }
        vsum += __shfl_xor_sync(0xffffffffu, vsum, 16);
        int c = lane & 15;
        float val = vsum * 0.125f + bias[c];
        float mx = val;
#pragma unroll
        for (int o = 8; o >= 1; o >>= 1) mx = fmaxf(mx, __shfl_xor_sync(0xffffffffu, mx, o));
        float se = expf(val - mx);
#pragma unroll
        for (int o = 8; o >= 1; o >>= 1) se += __shfl_xor_sync(0xffffffffu, se, o);
        float res = val - mx - logf(se);
        if (lane < 16) out[(size_t)n * C + c] = res;
    }
}

// ---------------- launch ----------------
extern "C" void kernel_launch(void* const* d_in, const int* in_sizes, int n_in,
                              void* d_out, int out_size) {
    const float* x   = (const float*)d_in[0];
    const int*   ei  = (const int*)d_in[1];
    const float* W1  = (const float*)d_in[2];
    const float* as1 = (const float*)d_in[3];
    const float* ad1 = (const float*)d_in[4];
    const float* b1  = (const float*)d_in[5];
    const float* W2  = (const float*)d_in[6];
    const float* as2 = (const float*)d_in[7];
    const float* ad2 = (const float*)d_in[8];
    const float* b2  = (const float*)d_in[9];
    const float* W3  = (const float*)d_in[10];
    const float* as3 = (const float*)d_in[11];
    const float* ad3 = (const float*)d_in[12];
    const float* b3  = (const float*)d_in[13];
    const float* p1  = (const float*)d_in[14];
    const float* p2  = (const float*)d_in[15];
    float* out = (float*)d_out;

    int N = in_sizes[0] / 256;
    int E = in_sizes[1] / 2;

    float *hbuf, *hpbuf;
    int *degptr;
    cudaGetSymbolAddress((void**)&hbuf, g_h);
    cudaGetSymbolAddress((void**)&hpbuf, g_hp);
    cudaGetSymbolAddress((void**)&degptr, g_deg);

    int gb256E = (E + 255) / 256;
    int gbAtt = (N * 8 + 255) / 256;
    int gbAgg = (N + 7) / 8;           // 8 warps/block
    int gbM = (N + 127) / 128;

    // CSR by destination (shared by all 3 layers)
    cudaMemsetAsync(degptr, 0, (size_t)N * sizeof(int));
    k_count<<<gb256E, 256>>>(ei, E);
    k_scan<<<1, 1024>>>(N, E);
    k_scatter<<<gb256E, 256>>>(ei, E);

    // Layer 1: h1 = x@W1 -> agg -> PReLU -> hp
    k_sgemm<<<dim3(gbM, 1), 128>>>(x, 256, nullptr, 0, W1, 64, hbuf, N);
    k_att<8><<<gbAtt, 256>>>(hbuf, as1, ad1, N);
    k_agg<8, 0><<<gbAgg, 256>>>(hbuf, b1, p1, hpbuf, N);

    // Layer 2: h2 = [x|hp]@W2 -> agg -> PReLU -> hp
    k_sgemm<<<dim3(gbM, 1), 128>>>(x, 256, hpbuf, 64, W2, 64, hbuf, N);
    k_att<8><<<gbAtt, 256>>>(hbuf, as2, ad2, N);
    k_agg<8, 0><<<gbAgg, 256>>>(hbuf, b2, p2, hpbuf, N);

    // Layer 3: h3 = hp@W3 -> agg(mean) -> log_softmax -> out
    k_sgemm<<<dim3(gbM, 2), 128>>>(hpbuf, 64, nullptr, 0, W3, 128, hbuf, N);
    k_att<16><<<gbAtt, 256>>>(hbuf, as3, ad3, N);
    k_agg<16, 1><<<gbAgg, 256>>>(hbuf, b3, nullptr, out, N);
}